// round 8
// baseline (speedup 1.0000x reference)
#include <cuda_runtime.h>
#include <stdint.h>

#define BATCH 4096
#define IN_F  2048
#define OUT_F 4096
#define WORDS (IN_F / 64)     // 32 u64 per row
#define NBLK  512             // must be <= co-resident capacity (148*4=592)

// Scratch (allocation-free: __device__ globals; zero-initialized at load)
__device__ uint64_t g_xbits[(size_t)BATCH * WORDS];
__device__ uint64_t g_pbits[(size_t)OUT_F * WORDS];
__device__ uint64_t g_xsig[BATCH];
__device__ uint64_t g_psig[OUT_F];
__device__ int g_arrive;      // two-phase counter: 0..NBLK (arrive), ..2*NBLK (reset)

// Exact verification: full 2048-bit compare. Equal sigs alone is never
// trusted — collisions cannot produce wrong output. .cg loads: post-barrier
// data written by other SMs.
__device__ __noinline__ bool fsu_full_cmp(int b, int o)
{
    const uint64_t* xb = &g_xbits[(size_t)b * WORDS];
    const uint64_t* pb = &g_pbits[(size_t)o * WORDS];
    #pragma unroll 8
    for (int k = 0; k < WORDS; ++k)
        if (__ldcg(xb + k) != __ldcg(pb + k)) return false;
    return true;
}

// -----------------------------------------------------------------------------
// Single fused kernel:
//   phase A (per block): zero-fill 8192 float4 of out + pack 16 rows
//            (each warp packs x-row gw and path-row gw; float4 loads,
//             4 ballots/iter — fixed bit permutation identical for both sides,
//             so packed-row equality <=> original-bit-row equality, exact)
//   grid barrier (atomic arrive + spin; all NBLK blocks are co-resident
//            by __launch_bounds__(256,4) => occupancy >= 4 blocks/SM)
//   phase B (per block): match 8 batch rows vs all 4096 psigs (brute-force
//            register compares), write verified 1.0s into pre-zeroed out.
//   reset  : two-phase counter returns g_arrive to 0 for the next graph replay.
// -----------------------------------------------------------------------------
__global__ __launch_bounds__(256, 4) void fsu_fused_kernel(
    const float* __restrict__ x,
    const float* __restrict__ w,
    const float* __restrict__ rng,
    float* __restrict__ out)
{
    const int tid  = threadIdx.x;
    const int wid  = tid >> 5;
    const int lane = tid & 31;

    // ---- phase A1: zero-fill this block's slice of out (pure store stream) ----
    {
        float4* outv = reinterpret_cast<float4*>(out);
        const float4 z = make_float4(0.0f, 0.0f, 0.0f, 0.0f);
        const int base = blockIdx.x * 8192;           // 4M float4 / 512 blocks
        #pragma unroll
        for (int k = 0; k < 32; ++k)
            outv[base + k * 256 + tid] = z;
    }

    // ---- phase A2: pack 2 rows per warp (x-row gw, then path-row gw) ----
    const int gw = blockIdx.x * 8 + wid;              // [0, 4096)
    const float rv = __ldg(rng);

    #pragma unroll
    for (int half = 0; half < 2; ++half) {
        const bool isX = (half == 0);
        const float4* src = reinterpret_cast<const float4*>(
            (isX ? x : w) + (size_t)gw * IN_F);

        uint64_t sig = 0;
        uint64_t myword = 0;

        #pragma unroll
        for (int it = 0; it < IN_F / 128; ++it) {     // 16 iterations
            const float4 v = __ldg(src + it * 32 + lane);
            bool b0, b1, b2, b3;
            if (isX) {
                b0 = (v.x > 0.5f); b1 = (v.y > 0.5f);
                b2 = (v.z > 0.5f); b3 = (v.w > 0.5f);
            } else {
                // BinGen/BSGen: prob=(w+1)*0.5; source=round(prob*256); bit = source > rng
                b0 = (rintf((v.x + 1.0f) * 0.5f * 256.0f) > rv);
                b1 = (rintf((v.y + 1.0f) * 0.5f * 256.0f) > rv);
                b2 = (rintf((v.z + 1.0f) * 0.5f * 256.0f) > rv);
                b3 = (rintf((v.w + 1.0f) * 0.5f * 256.0f) > rv);
            }
            const uint32_t m0 = __ballot_sync(0xFFFFFFFFu, b0);
            const uint32_t m1 = __ballot_sync(0xFFFFFFFFu, b1);
            const uint32_t m2 = __ballot_sync(0xFFFFFFFFu, b2);
            const uint32_t m3 = __ballot_sync(0xFFFFFFFFu, b3);
            const uint64_t wa = (uint64_t)m0 | ((uint64_t)m1 << 32);
            const uint64_t wb = (uint64_t)m2 | ((uint64_t)m3 << 32);
            if (lane == 2 * it)     myword = wa;
            if (lane == 2 * it + 1) myword = wb;
            sig = sig * 0x9E3779B97F4A7C15ull + wa;
            sig = sig * 0x9E3779B97F4A7C15ull + wb;
        }

        if (isX) {
            g_xbits[(size_t)gw * WORDS + lane] = myword;
            if (lane == 0) g_xsig[gw] = sig;
        } else {
            g_pbits[(size_t)gw * WORDS + lane] = myword;
            if (lane == 0) g_psig[gw] = sig;
        }
    }

    // ---- grid barrier: release our writes, arrive, spin until all arrived ----
    __syncthreads();
    __threadfence();
    if (tid == 0) {
        atomicAdd(&g_arrive, 1);
        volatile int* va = &g_arrive;
        while (*va < NBLK) { }
    }
    __syncthreads();
    __threadfence();   // acquire: other blocks' packed data now visible via L2

    // ---- phase B: match 8 batch rows vs all 4096 psigs ----
    {
        const int bbase = blockIdx.x * 8;
        uint64_t xs[8];
        #pragma unroll
        for (int r = 0; r < 8; ++r)
            xs[r] = __ldcg(&g_xsig[bbase + r]);

        #pragma unroll
        for (int k = 0; k < OUT_F / 256; ++k) {       // 16 psigs per thread
            const int o = k * 256 + tid;
            const uint64_t ps = __ldcg(&g_psig[o]);
            #pragma unroll
            for (int r = 0; r < 8; ++r) {
                if (ps == xs[r]) {
                    const int b = bbase + r;
                    if (fsu_full_cmp(b, o))
                        out[(size_t)b * OUT_F + o] = 1.0f;
                }
            }
        }
    }

    // ---- reset counter for next graph replay (two-phase: safe after all
    //      blocks passed the spin; last incrementer returns it to 0) ----
    __syncthreads();
    if (tid == 0) {
        const int v = atomicAdd(&g_arrive, 1);
        if (v == 2 * NBLK - 1) atomicExch(&g_arrive, 0);
    }
}

extern "C" void kernel_launch(void* const* d_in, const int* in_sizes, int n_in,
                              void* d_out, int out_size)
{
    const float* x   = (const float*)d_in[0];
    const float* w   = (const float*)d_in[1];
    const float* rng = (const float*)d_in[2];
    float* out = (float*)d_out;

    fsu_fused_kernel<<<NBLK, 256>>>(x, w, rng, out);
}

// round 9
// speedup vs baseline: 1.0164x; 1.0164x over previous
#include <cuda_runtime.h>
#include <stdint.h>

#define BATCH 4096
#define IN_F  2048
#define OUT_F 4096
#define WORDS (IN_F / 64)     // 32 u64 per row

// Scratch (allocation-free: __device__ globals)
__device__ uint64_t g_xbits[(size_t)BATCH * WORDS];
__device__ uint64_t g_pbits[(size_t)OUT_F * WORDS];
__device__ uint64_t g_xsig[BATCH];
__device__ uint64_t g_psig[OUT_F];

// -----------------------------------------------------------------------------
// Kernel 1: fused pack + zero-fill (HBM-bound: 64 MB read + 64 MB write).
//   1024 blocks x 256 threads. Each block packs 8 rows (one warp per row)
//   AND zero-fills a 4096-float4 slice of the output.
//   Pack: float4 loads, 4 ballots/iter. Bit order within packed words is a
//   fixed permutation of element order, identical for x and path rows, so
//   packed-row equality <=> original-bit-row equality (exact).
// -----------------------------------------------------------------------------
__global__ __launch_bounds__(256) void fsu_pack_zero_kernel(
    const float* __restrict__ x,
    const float* __restrict__ w,
    const float* __restrict__ rng,
    float4* __restrict__ outv)
{
    // ---- zero-fill slice (pure store stream, overlaps with pack loads) ----
    {
        const float4 z = make_float4(0.0f, 0.0f, 0.0f, 0.0f);
        const int base = blockIdx.x * 4096;          // 4M float4 / 1024 blocks
        #pragma unroll
        for (int k = 0; k < 16; ++k)
            outv[base + k * 256 + threadIdx.x] = z;
    }

    // ---- pack 8 rows (one warp per row) ----
    const int gwarp = (blockIdx.x * blockDim.x + threadIdx.x) >> 5;
    const int lane  = threadIdx.x & 31;
    const bool isX  = gwarp < BATCH;
    const int row   = isX ? gwarp : (gwarp - BATCH);

    const float rv = __ldg(rng);
    const float4* src = reinterpret_cast<const float4*>(
        (isX ? (x + (size_t)row * IN_F) : (w + (size_t)row * IN_F)));

    uint64_t sig = 0;
    uint64_t myword = 0;

    #pragma unroll
    for (int it = 0; it < IN_F / 128; ++it) {        // 16 iterations
        const float4 v = __ldg(src + it * 32 + lane);
        bool b0, b1, b2, b3;
        if (isX) {
            b0 = (v.x > 0.5f); b1 = (v.y > 0.5f);
            b2 = (v.z > 0.5f); b3 = (v.w > 0.5f);
        } else {
            // BinGen/BSGen: prob=(w+1)*0.5; source=round(prob*256); bit = source > rng
            b0 = (rintf((v.x + 1.0f) * 0.5f * 256.0f) > rv);
            b1 = (rintf((v.y + 1.0f) * 0.5f * 256.0f) > rv);
            b2 = (rintf((v.z + 1.0f) * 0.5f * 256.0f) > rv);
            b3 = (rintf((v.w + 1.0f) * 0.5f * 256.0f) > rv);
        }
        const uint32_t m0 = __ballot_sync(0xFFFFFFFFu, b0);
        const uint32_t m1 = __ballot_sync(0xFFFFFFFFu, b1);
        const uint32_t m2 = __ballot_sync(0xFFFFFFFFu, b2);
        const uint32_t m3 = __ballot_sync(0xFFFFFFFFu, b3);
        const uint64_t wa = (uint64_t)m0 | ((uint64_t)m1 << 32);
        const uint64_t wb = (uint64_t)m2 | ((uint64_t)m3 << 32);
        if (lane == 2 * it)     myword = wa;
        if (lane == 2 * it + 1) myword = wb;
        sig = sig * 0x9E3779B97F4A7C15ull + wa;
        sig = sig * 0x9E3779B97F4A7C15ull + wb;
    }

    if (isX) {
        g_xbits[(size_t)row * WORDS + lane] = myword;
        if (lane == 0) g_xsig[row] = sig;
    } else {
        g_pbits[(size_t)row * WORDS + lane] = myword;
        if (lane == 0) g_psig[row] = sig;
    }
}

// Exact verification: full 2048-bit compare. Equal sigs alone is never
// trusted — collisions cannot produce wrong output.
__device__ __noinline__ bool fsu_full_cmp(int b, int o)
{
    const uint64_t* xb = &g_xbits[(size_t)b * WORDS];
    const uint64_t* pb = &g_pbits[(size_t)o * WORDS];
    #pragma unroll 8
    for (int k = 0; k < WORDS; ++k)
        if (__ldg(xb + k) != __ldg(pb + k)) return false;
    return true;
}

// -----------------------------------------------------------------------------
// Kernel 2: brute-force sig matrix compare, launched with PDL so its launch
// and prologue overlap kernel 1. 512 blocks x 256 threads; block owns 8 batch
// rows (xs in 8 regs), each thread scans 16 psigs -> 128 independent register
// compares. Runs logically after kernel 1 (grid dependency), so out[] is
// already zeroed; verified matches (expected: none) written directly.
// -----------------------------------------------------------------------------
__global__ __launch_bounds__(256) void fsu_match_kernel(float* __restrict__ out)
{
    // Wait for kernel 1's writes to be visible (PDL dependency point).
    cudaGridDependencySynchronize();

    const int tid   = threadIdx.x;
    const int bbase = blockIdx.x * 8;

    uint64_t xs[8];
    #pragma unroll
    for (int r = 0; r < 8; ++r)
        xs[r] = __ldg(&g_xsig[bbase + r]);

    #pragma unroll
    for (int k = 0; k < OUT_F / 256; ++k) {          // 16 psigs per thread
        const int o = k * 256 + tid;
        const uint64_t ps = __ldg(&g_psig[o]);
        #pragma unroll
        for (int r = 0; r < 8; ++r) {
            if (ps == xs[r]) {
                const int b = bbase + r;
                if (fsu_full_cmp(b, o))
                    out[(size_t)b * OUT_F + o] = 1.0f;
            }
        }
    }
}

extern "C" void kernel_launch(void* const* d_in, const int* in_sizes, int n_in,
                              void* d_out, int out_size)
{
    const float* x   = (const float*)d_in[0];
    const float* w   = (const float*)d_in[1];
    const float* rng = (const float*)d_in[2];
    float* out = (float*)d_out;

    // Kernel 1: (BATCH + OUT_F) warps = 8192 -> 1024 blocks of 8 warps; each
    // block also zero-fills 4096 float4 of the output.
    fsu_pack_zero_kernel<<<1024, 256>>>(x, w, rng,
                                        reinterpret_cast<float4*>(out));

    // Kernel 2 with programmatic dependent launch: overlap launch/prologue
    // with kernel 1's tail; cudaGridDependencySynchronize() inside gates the
    // actual data reads.
    cudaLaunchConfig_t cfg = {};
    cfg.gridDim  = dim3(BATCH / 8);   // 512
    cfg.blockDim = dim3(256);
    cfg.dynamicSmemBytes = 0;
    cfg.stream = 0;                   // same (legacy default) stream as <<<>>>
    cudaLaunchAttribute attrs[1];
    attrs[0].id = cudaLaunchAttributeProgrammaticStreamSerialization;
    attrs[0].val.programmaticStreamSerializationAllowed = 1;
    cfg.attrs = attrs;
    cfg.numAttrs = 1;
    cudaLaunchKernelEx(&cfg, fsu_match_kernel, out);
}